// round 1
// baseline (speedup 1.0000x reference)
#include <cuda_runtime.h>
#include <math.h>
#include <stdint.h>

// Problem constants
#define Bn     4
#define Ln     4096
#define Dn     256
#define DIn    512
#define NST    16
#define Mn     (Bn * Ln)      // 16384
#define XZW    (2 * DIn)      // 1024
#define XDW    48             // dt_rank + 2*n = 16 + 32
#define NLn    4

// ---------------- scratch (static device memory; no allocation) ----------
// offsets in floats
#define OFF_XZ     0u
#define OFF_XC     16777216u
#define OFF_XDBL   25165824u
#define OFF_DELTA  25952256u
#define OFF_YS     34340864u
#define OFF_AQ     42729472u
#define OFF_ATTN   46923776u
#define OFF_Q      51118080u
#define OFF_XF     55312384u
#define OFF_FFH    59506688u
#define OFF_FFO    63700992u
#define OFF_MVEC   67895296u
#define SCRATCH_TOTAL 67911680u   // ~272 MB

__device__ __align__(16) float g_scratch[SCRATCH_TOTAL];

// ---------------- math helpers ----------------
__device__ __forceinline__ float sigmoidf_(float x) { return 1.f / (1.f + __expf(-x)); }
__device__ __forceinline__ float siluf_(float x)    { return x * sigmoidf_(x); }
__device__ __forceinline__ float softplusf_(float x){ return fmaxf(x, 0.f) + log1pf(__expf(-fabsf(x))); }

// ---------------- GEMM: C[m,n] = act( sum_k A[m,k]*W[n,k] + bias[n] ) ----
// A: (M,K) row stride lda; W: (N,K) contiguous; C: (M,N) contiguous.
// BM=128, BN=64, BK=16, 256 threads, 8x4 per thread.
// Requires: M % 128 == 0, K % 16 == 0, N % 4 == 0, lda % 4 == 0.
#define GBM 128
#define GBN 64
#define GBK 16

template <int ACT, bool HAS_BIAS>
__global__ void __launch_bounds__(256) gemm_nt_kernel(
    const float* __restrict__ A, int lda,
    const float* __restrict__ W,
    const float* __restrict__ bias,
    float* __restrict__ C,
    int Mtot, int Ntot, int Ktot)
{
    __shared__ float As[GBK][GBM];
    __shared__ float Ws[GBK][GBN];

    const int tid = threadIdx.x;
    const int tx = tid & 15;        // 0..15 -> N
    const int ty = tid >> 4;        // 0..15 -> M
    const int bm = blockIdx.y * GBM;
    const int bn = blockIdx.x * GBN;

    float acc[8][4];
#pragma unroll
    for (int i = 0; i < 8; i++)
#pragma unroll
        for (int j = 0; j < 4; j++) acc[i][j] = 0.f;

    for (int k0 = 0; k0 < Ktot; k0 += GBK) {
        // load A tile (128x16) transposed into As[k][m]
#pragma unroll
        for (int p = 0; p < 2; p++) {
            int t   = tid + p * 256;
            int row = t >> 2;            // 0..127
            int kc  = (t & 3) << 2;      // 0,4,8,12
            const float4 av = *(const float4*)(A + (size_t)(bm + row) * lda + k0 + kc);
            As[kc + 0][row] = av.x;
            As[kc + 1][row] = av.y;
            As[kc + 2][row] = av.z;
            As[kc + 3][row] = av.w;
        }
        // load W tile (64x16) transposed into Ws[k][n]
        {
            int row = tid >> 2;          // 0..63
            int kc  = (tid & 3) << 2;
            int gn  = bn + row;
            float4 wv = make_float4(0.f, 0.f, 0.f, 0.f);
            if (gn < Ntot) wv = *(const float4*)(W + (size_t)gn * Ktot + k0 + kc);
            Ws[kc + 0][row] = wv.x;
            Ws[kc + 1][row] = wv.y;
            Ws[kc + 2][row] = wv.z;
            Ws[kc + 3][row] = wv.w;
        }
        __syncthreads();

#pragma unroll
        for (int kk = 0; kk < GBK; kk++) {
            float4 a0 = *(const float4*)&As[kk][ty * 4];
            float4 a1 = *(const float4*)&As[kk][64 + ty * 4];
            float4 w  = *(const float4*)&Ws[kk][tx * 4];
            float am[8] = {a0.x, a0.y, a0.z, a0.w, a1.x, a1.y, a1.z, a1.w};
            float wn[4] = {w.x, w.y, w.z, w.w};
#pragma unroll
            for (int i = 0; i < 8; i++)
#pragma unroll
                for (int j = 0; j < 4; j++)
                    acc[i][j] = fmaf(am[i], wn[j], acc[i][j]);
        }
        __syncthreads();
    }

    const int n0 = bn + tx * 4;
    if (n0 >= Ntot) return;
    float bz[4] = {0.f, 0.f, 0.f, 0.f};
    if (HAS_BIAS) {
        float4 bv = *(const float4*)(bias + n0);
        bz[0] = bv.x; bz[1] = bv.y; bz[2] = bv.z; bz[3] = bv.w;
    }
#pragma unroll
    for (int i = 0; i < 8; i++) {
        int m = bm + ((i < 4) ? (ty * 4 + i) : (64 + ty * 4 + (i - 4)));
        float v[4];
#pragma unroll
        for (int j = 0; j < 4; j++) {
            float c = acc[i][j] + bz[j];
            if (ACT == 1) c = fmaxf(c, 0.f);
            if (ACT == 2) c = softplusf_(c);
            v[j] = c;
        }
        *(float4*)(C + (size_t)m * Ntot + n0) = make_float4(v[0], v[1], v[2], v[3]);
    }
}

// ---------------- modulation vectors: m = silu(ts) @ W.T + b ------------
// mvec layout: [layer][which][b][512]; grid = NL*2*B blocks, 512 threads.
__global__ void modvec_kernel(const float* __restrict__ ts,
                              const float* __restrict__ attn_W, const float* __restrict__ attn_b,
                              const float* __restrict__ ff_W,   const float* __restrict__ ff_b,
                              float* __restrict__ mvec)
{
    __shared__ float st[Dn];
    const int layer = blockIdx.x >> 3;
    const int which = (blockIdx.x >> 2) & 1;
    const int b     = blockIdx.x & 3;
    if (threadIdx.x < Dn) {
        float tv = ts[b * Dn + threadIdx.x];
        st[threadIdx.x] = siluf_(tv);
    }
    __syncthreads();
    const int j = threadIdx.x;  // 0..511
    const float* W    = (which ? ff_W : attn_W) + (size_t)layer * 2 * Dn * Dn + (size_t)j * Dn;
    const float* bias = (which ? ff_b : attn_b) + layer * 2 * Dn;
    float acc = bias[j];
#pragma unroll 4
    for (int k = 0; k < Dn; k += 4) {
        float4 wv = *(const float4*)(W + k);
        acc = fmaf(st[k], wv.x, acc);
        acc = fmaf(st[k + 1], wv.y, acc);
        acc = fmaf(st[k + 2], wv.z, acc);
        acc = fmaf(st[k + 3], wv.w, acc);
    }
    mvec[((layer * 2 + which) * Bn + b) * 2 * Dn + j] = acc;
}

// ---------------- AdaLN apply: out = q*(1+scale) + shift ---------------
// mv: per-layer base [B][512]; grid*block = Mn*64 threads (float4 per thread).
__global__ void adaln_kernel(const float* __restrict__ q,
                             const float* __restrict__ mv,
                             float* __restrict__ out)
{
    int idx = blockIdx.x * blockDim.x + threadIdx.x;   // Mn * 64
    int row = idx >> 6;
    int c4  = (idx & 63) << 2;
    int b   = row >> 12;                               // L = 4096
    float4 qv = *(const float4*)(q + (size_t)row * Dn + c4);
    float4 s  = *(const float4*)(mv + b * 2 * Dn + c4);
    float4 sh = *(const float4*)(mv + b * 2 * Dn + Dn + c4);
    float4 o;
    o.x = fmaf(qv.x, 1.f + s.x, sh.x);
    o.y = fmaf(qv.y, 1.f + s.y, sh.y);
    o.z = fmaf(qv.z, 1.f + s.z, sh.z);
    o.w = fmaf(qv.w, 1.f + s.w, sh.w);
    *(float4*)(out + (size_t)row * Dn + c4) = o;
}

// ---------------- causal depthwise conv (width 4) + SiLU ---------------
// xi = first half of xz rows (stride XZW). out: xc (Mn x DIn).
__global__ void conv_silu_kernel(const float* __restrict__ xz,
                                 const float* __restrict__ cw,
                                 const float* __restrict__ cb,
                                 float* __restrict__ xc)
{
    int idx = blockIdx.x * blockDim.x + threadIdx.x;   // Mn * 128
    int d4  = (idx & 127) << 2;
    int row = idx >> 7;
    int b   = row >> 12;
    int l   = row & 4095;

    float4 bv = *(const float4*)(cb + d4);
    float acc[4] = {bv.x, bv.y, bv.z, bv.w};
    float4 w0 = *(const float4*)(cw + (d4 + 0) * 4);
    float4 w1 = *(const float4*)(cw + (d4 + 1) * 4);
    float4 w2 = *(const float4*)(cw + (d4 + 2) * 4);
    float4 w3 = *(const float4*)(cw + (d4 + 3) * 4);
    const float* wr[4] = {&w0.x, &w1.x, &w2.x, &w3.x};

#pragma unroll
    for (int t = 0; t < 4; t++) {
        int lt = l - 3 + t;
        if (lt < 0) continue;
        const float4 xv = *(const float4*)(xz + (size_t)(b * Ln + lt) * XZW + d4);
        acc[0] = fmaf(xv.x, wr[0][t], acc[0]);
        acc[1] = fmaf(xv.y, wr[1][t], acc[1]);
        acc[2] = fmaf(xv.z, wr[2][t], acc[2]);
        acc[3] = fmaf(xv.w, wr[3][t], acc[3]);
    }
    float4 o = make_float4(siluf_(acc[0]), siluf_(acc[1]), siluf_(acc[2]), siluf_(acc[3]));
    *(float4*)(xc + (size_t)row * DIn + d4) = o;
}

// ---------------- selective scan ----------------
// lane = (group of 16) state index n; each warp handles 2 (b,d) channels.
// grid 256 x 128 threads -> 2048 channels.
__global__ void scan_kernel(const float* __restrict__ xdbl,
                            const float* __restrict__ delta,
                            const float* __restrict__ xc,
                            const float* __restrict__ xz,
                            const float* __restrict__ A_log,
                            const float* __restrict__ D_p,
                            float* __restrict__ ys)
{
    const int tid  = threadIdx.x;
    const int warp = tid >> 5, lane = tid & 31;
    const int grp  = lane >> 4, n = lane & 15;
    const int ch   = blockIdx.x * 8 + warp * 2 + grp;
    const int b    = ch >> 9, d = ch & 511;

    const float Acoef = -__expf(A_log[d * NST + n]);
    const float Dp    = D_p[d];
    float h = 0.f;

    const float* xdb = xdbl  + (size_t)b * Ln * XDW;
    const float* dl  = delta + (size_t)b * Ln * DIn + d;
    const float* xcb = xc    + (size_t)b * Ln * DIn + d;
    const float* zb  = xz    + (size_t)b * Ln * XZW + DIn + d;
    float*       yb  = ys    + (size_t)b * Ln * DIn + d;

#pragma unroll 2
    for (int t = 0; t < Ln; t++) {
        float Bv  = xdb[t * XDW + 16 + n];
        float Cv  = xdb[t * XDW + 32 + n];
        float dlt = dl[(size_t)t * DIn];
        float xv  = xcb[(size_t)t * DIn];
        float dA  = __expf(dlt * Acoef);
        h = fmaf(dA, h, (dlt * xv) * Bv);
        float p = h * Cv;
        p += __shfl_xor_sync(0xffffffffu, p, 1);
        p += __shfl_xor_sync(0xffffffffu, p, 2);
        p += __shfl_xor_sync(0xffffffffu, p, 4);
        p += __shfl_xor_sync(0xffffffffu, p, 8);
        if (n == 0) {
            float zv = zb[(size_t)t * XZW];
            float y  = p + xv * Dp;
            yb[(size_t)t * DIn] = y * siluf_(zv);
        }
    }
}

// ---------------- residual + LayerNorm (row = 256) ----------------------
// out = LN(x + r); one warp per row, 8 rows per 256-thread block.
__global__ void ln_res_kernel(const float* __restrict__ x,
                              const float* __restrict__ r,
                              const float* __restrict__ w,
                              const float* __restrict__ bb,
                              float* __restrict__ out)
{
    const int row  = blockIdx.x * 8 + (threadIdx.x >> 5);
    const int lane = threadIdx.x & 31;
    const float* xr = x + (size_t)row * Dn;
    const float* rr = r + (size_t)row * Dn;

    float v[8];
#pragma unroll
    for (int p = 0; p < 2; p++) {
        float4 a = *(const float4*)(xr + p * 128 + lane * 4);
        float4 c = *(const float4*)(rr + p * 128 + lane * 4);
        v[p * 4 + 0] = a.x + c.x;
        v[p * 4 + 1] = a.y + c.y;
        v[p * 4 + 2] = a.z + c.z;
        v[p * 4 + 3] = a.w + c.w;
    }
    float s = 0.f;
#pragma unroll
    for (int i = 0; i < 8; i++) s += v[i];
#pragma unroll
    for (int o = 16; o > 0; o >>= 1) s += __shfl_xor_sync(0xffffffffu, s, o);
    float mu = s * (1.f / 256.f);
    float q = 0.f;
#pragma unroll
    for (int i = 0; i < 8; i++) { float dd = v[i] - mu; q = fmaf(dd, dd, q); }
#pragma unroll
    for (int o = 16; o > 0; o >>= 1) q += __shfl_xor_sync(0xffffffffu, q, o);
    float inv = rsqrtf(q * (1.f / 256.f) + 1e-5f);

#pragma unroll
    for (int p = 0; p < 2; p++) {
        int c0 = p * 128 + lane * 4;
        float4 wv = *(const float4*)(w + c0);
        float4 bv = *(const float4*)(bb + c0);
        float4 o;
        o.x = (v[p * 4 + 0] - mu) * inv * wv.x + bv.x;
        o.y = (v[p * 4 + 1] - mu) * inv * wv.y + bv.y;
        o.z = (v[p * 4 + 2] - mu) * inv * wv.z + bv.z;
        o.w = (v[p * 4 + 3] - mu) * inv * wv.w + bv.w;
        *(float4*)(out + (size_t)row * Dn + c0) = o;
    }
}

// ---------------- host launch ----------------
extern "C" void kernel_launch(void* const* d_in, const int* in_sizes, int n_in,
                              void* d_out, int out_size)
{
    const float* query      = (const float*)d_in[0];
    const float* diff_ts    = (const float*)d_in[2];
    const float* W_in       = (const float*)d_in[3];
    const float* conv_w     = (const float*)d_in[4];
    const float* conv_b     = (const float*)d_in[5];
    const float* W_x        = (const float*)d_in[6];
    const float* W_dt       = (const float*)d_in[7];
    const float* b_dt       = (const float*)d_in[8];
    const float* A_log      = (const float*)d_in[9];
    const float* D_p        = (const float*)d_in[10];
    const float* W_out      = (const float*)d_in[11];
    const float* attn_ada_W = (const float*)d_in[12];
    const float* attn_ada_b = (const float*)d_in[13];
    const float* attn_ln_w  = (const float*)d_in[14];
    const float* attn_ln_b  = (const float*)d_in[15];
    const float* ff_W1      = (const float*)d_in[16];
    const float* ff_b1      = (const float*)d_in[17];
    const float* ff_W2      = (const float*)d_in[18];
    const float* ff_b2      = (const float*)d_in[19];
    const float* ff_ln_w    = (const float*)d_in[20];
    const float* ff_ln_b    = (const float*)d_in[21];
    const float* ff_ada_W   = (const float*)d_in[22];
    const float* ff_ada_b   = (const float*)d_in[23];
    float* out = (float*)d_out;

    float* sc = nullptr;
    cudaGetSymbolAddress((void**)&sc, g_scratch);
    float* g_xz    = sc + OFF_XZ;
    float* g_xc    = sc + OFF_XC;
    float* g_xdbl  = sc + OFF_XDBL;
    float* g_delta = sc + OFF_DELTA;
    float* g_ys    = sc + OFF_YS;
    float* g_aq    = sc + OFF_AQ;
    float* g_attn  = sc + OFF_ATTN;
    float* g_q     = sc + OFF_Q;
    float* g_xf    = sc + OFF_XF;
    float* g_ffh   = sc + OFF_FFH;
    float* g_ffo   = sc + OFF_FFO;
    float* g_mvec  = sc + OFF_MVEC;

    // all modulation vectors for all layers up front
    modvec_kernel<<<NLn * 2 * Bn, 512>>>(diff_ts, attn_ada_W, attn_ada_b,
                                         ff_ada_W, ff_ada_b, g_mvec);

    const int adaln_blocks = (Mn * 64) / 256;   // 4096
    const int conv_blocks  = (Mn * 128) / 256;  // 8192

    for (int i = 0; i < NLn; i++) {
        const float* qin = (i == 0) ? query : (out + (size_t)(i - 1) * Mn * Dn);

        // AdaLN (attn)
        adaln_kernel<<<adaln_blocks, 256>>>(qin, g_mvec + (size_t)(i * 2 + 0) * Bn * 2 * Dn, g_aq);

        // xz = aq @ W_in.T       (M,1024)
        gemm_nt_kernel<0, false><<<dim3(XZW / GBN, Mn / GBM), 256>>>(
            g_aq, Dn, W_in + (size_t)i * XZW * Dn, nullptr, g_xz, Mn, XZW, Dn);

        // causal conv + silu -> xc (M,512)
        conv_silu_kernel<<<conv_blocks, 256>>>(g_xz, conv_w + (size_t)i * DIn * 4,
                                               conv_b + (size_t)i * DIn, g_xc);

        // x_dbl = xc @ W_x.T     (M,48)
        gemm_nt_kernel<0, false><<<dim3(1, Mn / GBM), 256>>>(
            g_xc, DIn, W_x + (size_t)i * XDW * DIn, nullptr, g_xdbl, Mn, XDW, DIn);

        // delta = softplus(dt @ W_dt.T + b_dt)   (M,512); dt = x_dbl[:, :16] (lda=48)
        gemm_nt_kernel<2, true><<<dim3(DIn / GBN, Mn / GBM), 256>>>(
            g_xdbl, XDW, W_dt + (size_t)i * DIn * 16, b_dt + (size_t)i * DIn,
            g_delta, Mn, DIn, 16);

        // selective scan -> ys (M,512)
        scan_kernel<<<256, 128>>>(g_xdbl, g_delta, g_xc, g_xz,
                                  A_log + (size_t)i * DIn * NST, D_p + (size_t)i * DIn, g_ys);

        // attn = ys @ W_out.T    (M,256)
        gemm_nt_kernel<0, false><<<dim3(Dn / GBN, Mn / GBM), 256>>>(
            g_ys, DIn, W_out + (size_t)i * Dn * DIn, nullptr, g_attn, Mn, Dn, DIn);

        // query = LN(qin + attn)
        ln_res_kernel<<<Mn / 8, 256>>>(qin, g_attn, attn_ln_w + (size_t)i * Dn,
                                       attn_ln_b + (size_t)i * Dn, g_q);

        // AdaLN (ff) -> xf
        adaln_kernel<<<adaln_blocks, 256>>>(g_q, g_mvec + (size_t)(i * 2 + 1) * Bn * 2 * Dn, g_xf);

        // h = relu(xf @ ff_W1.T + b1)
        gemm_nt_kernel<1, true><<<dim3(Dn / GBN, Mn / GBM), 256>>>(
            g_xf, Dn, ff_W1 + (size_t)i * Dn * Dn, ff_b1 + (size_t)i * Dn, g_ffh, Mn, Dn, Dn);

        // o = h @ ff_W2.T + b2
        gemm_nt_kernel<0, true><<<dim3(Dn / GBN, Mn / GBM), 256>>>(
            g_ffh, Dn, ff_W2 + (size_t)i * Dn * Dn, ff_b2 + (size_t)i * Dn, g_ffo, Mn, Dn, Dn);

        // layer output = LN(xf + o)
        ln_res_kernel<<<Mn / 8, 256>>>(g_xf, g_ffo, ff_ln_w + (size_t)i * Dn,
                                       ff_ln_b + (size_t)i * Dn, out + (size_t)i * Mn * Dn);
    }
}

// round 2
// speedup vs baseline: 4.1483x; 4.1483x over previous
#include <cuda_runtime.h>
#include <math.h>
#include <stdint.h>

// Problem constants
#define Bn     4
#define Ln     4096
#define Dn     256
#define DIn    512
#define NST    16
#define Mn     (Bn * Ln)      // 16384
#define XZW    (2 * DIn)      // 1024
#define XDW    48             // dt_rank + 2*n = 16 + 32
#define NLn    4
#define CH     (Bn * DIn)     // 2048 scan channels
#define NC     64             // scan chunks
#define CL     64             // chunk length (NC*CL = Ln)

// ---------------- scratch (static device memory; no allocation) ----------
#define OFF_XZ     0u
#define OFF_XC     16777216u
#define OFF_XDBL   25165824u
#define OFF_DELTA  25952256u
#define OFF_YS     34340864u
#define OFF_AQ     42729472u
#define OFF_ATTN   46923776u
#define OFF_Q      51118080u
#define OFF_XF     55312384u
#define OFF_FFH    59506688u
#define OFF_FFO    63700992u
#define OFF_MVEC   67895296u
#define OFF_P      67911680u
#define OFF_S      70008832u
#define OFF_H0     72105984u
#define SCRATCH_TOTAL 74203136u   // ~297 MB

__device__ __align__(16) float g_scratch[SCRATCH_TOTAL];

// ---------------- math helpers ----------------
__device__ __forceinline__ float sigmoidf_(float x) { return 1.f / (1.f + __expf(-x)); }
__device__ __forceinline__ float siluf_(float x)    { return x * sigmoidf_(x); }
__device__ __forceinline__ float softplusf_(float x){ return fmaxf(x, 0.f) + log1pf(__expf(-fabsf(x))); }

// =========================================================================
// GEMM 128x128x16, 256 threads, 8x8 microtile (split 4+4 halves at +64).
// C[m,n] = act( sum_k A[m,k]*W[n,k] + bias[n] )
// A: (M,K) row stride lda; W: (N,K) contiguous row-major; C: (M,N).
// Requires M%128==0, N%128==0, K%16==0.
// =========================================================================
#define TBM 128
#define TBN 128
#define TBK 16

template <int ACT, bool HAS_BIAS>
__global__ void __launch_bounds__(256) gemm128_kernel(
    const float* __restrict__ A, int lda,
    const float* __restrict__ W,
    const float* __restrict__ bias,
    float* __restrict__ C,
    int Ntot, int Ktot)
{
    __shared__ float As[TBK][TBM];
    __shared__ float Bs[TBK][TBN];

    const int tid = threadIdx.x;
    const int tx = tid & 15;        // n group
    const int ty = tid >> 4;        // m group
    const int bm = blockIdx.y * TBM;
    const int bn = blockIdx.x * TBN;

    const int lrow = tid >> 1;          // 0..127
    const int lk   = (tid & 1) * 8;     // 0 or 8
    const float* Ap = A + (size_t)(bm + lrow) * lda + lk;
    const float* Wp = W + (size_t)(bn + lrow) * Ktot + lk;

    float acc[8][8];
#pragma unroll
    for (int i = 0; i < 8; i++)
#pragma unroll
        for (int j = 0; j < 8; j++) acc[i][j] = 0.f;

    for (int k0 = 0; k0 < Ktot; k0 += TBK) {
        float4 a0 = *(const float4*)(Ap + k0);
        float4 a1 = *(const float4*)(Ap + k0 + 4);
        float4 w0 = *(const float4*)(Wp + k0);
        float4 w1 = *(const float4*)(Wp + k0 + 4);
        As[lk + 0][lrow] = a0.x; As[lk + 1][lrow] = a0.y;
        As[lk + 2][lrow] = a0.z; As[lk + 3][lrow] = a0.w;
        As[lk + 4][lrow] = a1.x; As[lk + 5][lrow] = a1.y;
        As[lk + 6][lrow] = a1.z; As[lk + 7][lrow] = a1.w;
        Bs[lk + 0][lrow] = w0.x; Bs[lk + 1][lrow] = w0.y;
        Bs[lk + 2][lrow] = w0.z; Bs[lk + 3][lrow] = w0.w;
        Bs[lk + 4][lrow] = w1.x; Bs[lk + 5][lrow] = w1.y;
        Bs[lk + 6][lrow] = w1.z; Bs[lk + 7][lrow] = w1.w;
        __syncthreads();

#pragma unroll
        for (int kk = 0; kk < TBK; kk++) {
            float4 am0 = *(const float4*)&As[kk][ty * 4];
            float4 am1 = *(const float4*)&As[kk][64 + ty * 4];
            float4 bn0 = *(const float4*)&Bs[kk][tx * 4];
            float4 bn1 = *(const float4*)&Bs[kk][64 + tx * 4];
            float am[8] = {am0.x, am0.y, am0.z, am0.w, am1.x, am1.y, am1.z, am1.w};
            float bv[8] = {bn0.x, bn0.y, bn0.z, bn0.w, bn1.x, bn1.y, bn1.z, bn1.w};
#pragma unroll
            for (int i = 0; i < 8; i++)
#pragma unroll
                for (int j = 0; j < 8; j++)
                    acc[i][j] = fmaf(am[i], bv[j], acc[i][j]);
        }
        __syncthreads();
    }

    float bz[8];
#pragma unroll
    for (int j = 0; j < 8; j++) bz[j] = 0.f;
    if (HAS_BIAS) {
        float4 b0 = *(const float4*)(bias + bn + tx * 4);
        float4 b1 = *(const float4*)(bias + bn + 64 + tx * 4);
        bz[0] = b0.x; bz[1] = b0.y; bz[2] = b0.z; bz[3] = b0.w;
        bz[4] = b1.x; bz[5] = b1.y; bz[6] = b1.z; bz[7] = b1.w;
    }
#pragma unroll
    for (int i = 0; i < 8; i++) {
        int m = bm + ((i < 4) ? (ty * 4 + i) : (64 + ty * 4 + (i - 4)));
        float v[8];
#pragma unroll
        for (int j = 0; j < 8; j++) {
            float c = acc[i][j] + bz[j];
            if (ACT == 1) c = fmaxf(c, 0.f);
            if (ACT == 2) c = softplusf_(c);
            v[j] = c;
        }
        *(float4*)(C + (size_t)m * Ntot + bn + tx * 4) = make_float4(v[0], v[1], v[2], v[3]);
        *(float4*)(C + (size_t)m * Ntot + bn + 64 + tx * 4) = make_float4(v[4], v[5], v[6], v[7]);
    }
}

// ---------------- narrow GEMM (128x64x16) for N=48 (x_dbl) --------------
#define GBM 128
#define GBN 64
#define GBK 16

template <int ACT, bool HAS_BIAS>
__global__ void __launch_bounds__(256) gemm_nt_kernel(
    const float* __restrict__ A, int lda,
    const float* __restrict__ W,
    const float* __restrict__ bias,
    float* __restrict__ C,
    int Mtot, int Ntot, int Ktot)
{
    __shared__ float As[GBK][GBM];
    __shared__ float Ws[GBK][GBN];

    const int tid = threadIdx.x;
    const int tx = tid & 15;
    const int ty = tid >> 4;
    const int bm = blockIdx.y * GBM;
    const int bn = blockIdx.x * GBN;

    float acc[8][4];
#pragma unroll
    for (int i = 0; i < 8; i++)
#pragma unroll
        for (int j = 0; j < 4; j++) acc[i][j] = 0.f;

    for (int k0 = 0; k0 < Ktot; k0 += GBK) {
#pragma unroll
        for (int p = 0; p < 2; p++) {
            int t   = tid + p * 256;
            int row = t >> 2;
            int kc  = (t & 3) << 2;
            const float4 av = *(const float4*)(A + (size_t)(bm + row) * lda + k0 + kc);
            As[kc + 0][row] = av.x;
            As[kc + 1][row] = av.y;
            As[kc + 2][row] = av.z;
            As[kc + 3][row] = av.w;
        }
        {
            int row = tid >> 2;
            int kc  = (tid & 3) << 2;
            int gn  = bn + row;
            float4 wv = make_float4(0.f, 0.f, 0.f, 0.f);
            if (gn < Ntot) wv = *(const float4*)(W + (size_t)gn * Ktot + k0 + kc);
            Ws[kc + 0][row] = wv.x;
            Ws[kc + 1][row] = wv.y;
            Ws[kc + 2][row] = wv.z;
            Ws[kc + 3][row] = wv.w;
        }
        __syncthreads();

#pragma unroll
        for (int kk = 0; kk < GBK; kk++) {
            float4 a0 = *(const float4*)&As[kk][ty * 4];
            float4 a1 = *(const float4*)&As[kk][64 + ty * 4];
            float4 w  = *(const float4*)&Ws[kk][tx * 4];
            float am[8] = {a0.x, a0.y, a0.z, a0.w, a1.x, a1.y, a1.z, a1.w};
            float wn[4] = {w.x, w.y, w.z, w.w};
#pragma unroll
            for (int i = 0; i < 8; i++)
#pragma unroll
                for (int j = 0; j < 4; j++)
                    acc[i][j] = fmaf(am[i], wn[j], acc[i][j]);
        }
        __syncthreads();
    }

    const int n0 = bn + tx * 4;
    if (n0 >= Ntot) return;
    float bz[4] = {0.f, 0.f, 0.f, 0.f};
    if (HAS_BIAS) {
        float4 bv = *(const float4*)(bias + n0);
        bz[0] = bv.x; bz[1] = bv.y; bz[2] = bv.z; bz[3] = bv.w;
    }
#pragma unroll
    for (int i = 0; i < 8; i++) {
        int m = bm + ((i < 4) ? (ty * 4 + i) : (64 + ty * 4 + (i - 4)));
        float v[4];
#pragma unroll
        for (int j = 0; j < 4; j++) {
            float c = acc[i][j] + bz[j];
            if (ACT == 1) c = fmaxf(c, 0.f);
            if (ACT == 2) c = softplusf_(c);
            v[j] = c;
        }
        *(float4*)(C + (size_t)m * Ntot + n0) = make_float4(v[0], v[1], v[2], v[3]);
    }
}

// ---------------- modulation vectors: m = silu(ts) @ W.T + b ------------
__global__ void modvec_kernel(const float* __restrict__ ts,
                              const float* __restrict__ attn_W, const float* __restrict__ attn_b,
                              const float* __restrict__ ff_W,   const float* __restrict__ ff_b,
                              float* __restrict__ mvec)
{
    __shared__ float st[Dn];
    const int layer = blockIdx.x >> 3;
    const int which = (blockIdx.x >> 2) & 1;
    const int b     = blockIdx.x & 3;
    if (threadIdx.x < Dn) {
        float tv = ts[b * Dn + threadIdx.x];
        st[threadIdx.x] = siluf_(tv);
    }
    __syncthreads();
    const int j = threadIdx.x;
    const float* W    = (which ? ff_W : attn_W) + (size_t)layer * 2 * Dn * Dn + (size_t)j * Dn;
    const float* bias = (which ? ff_b : attn_b) + layer * 2 * Dn;
    float acc = bias[j];
#pragma unroll 4
    for (int k = 0; k < Dn; k += 4) {
        float4 wv = *(const float4*)(W + k);
        acc = fmaf(st[k], wv.x, acc);
        acc = fmaf(st[k + 1], wv.y, acc);
        acc = fmaf(st[k + 2], wv.z, acc);
        acc = fmaf(st[k + 3], wv.w, acc);
    }
    mvec[((layer * 2 + which) * Bn + b) * 2 * Dn + j] = acc;
}

// ---------------- AdaLN apply ----------------
__global__ void adaln_kernel(const float* __restrict__ q,
                             const float* __restrict__ mv,
                             float* __restrict__ out)
{
    int idx = blockIdx.x * blockDim.x + threadIdx.x;
    int row = idx >> 6;
    int c4  = (idx & 63) << 2;
    int b   = row >> 12;
    float4 qv = *(const float4*)(q + (size_t)row * Dn + c4);
    float4 s  = *(const float4*)(mv + b * 2 * Dn + c4);
    float4 sh = *(const float4*)(mv + b * 2 * Dn + Dn + c4);
    float4 o;
    o.x = fmaf(qv.x, 1.f + s.x, sh.x);
    o.y = fmaf(qv.y, 1.f + s.y, sh.y);
    o.z = fmaf(qv.z, 1.f + s.z, sh.z);
    o.w = fmaf(qv.w, 1.f + s.w, sh.w);
    *(float4*)(out + (size_t)row * Dn + c4) = o;
}

// ---------------- causal depthwise conv (width 4) + SiLU ---------------
__global__ void conv_silu_kernel(const float* __restrict__ xz,
                                 const float* __restrict__ cw,
                                 const float* __restrict__ cb,
                                 float* __restrict__ xc)
{
    int idx = blockIdx.x * blockDim.x + threadIdx.x;
    int d4  = (idx & 127) << 2;
    int row = idx >> 7;
    int b   = row >> 12;
    int l   = row & 4095;

    float4 bv = *(const float4*)(cb + d4);
    float acc[4] = {bv.x, bv.y, bv.z, bv.w};
    float4 w0 = *(const float4*)(cw + (d4 + 0) * 4);
    float4 w1 = *(const float4*)(cw + (d4 + 1) * 4);
    float4 w2 = *(const float4*)(cw + (d4 + 2) * 4);
    float4 w3 = *(const float4*)(cw + (d4 + 3) * 4);
    const float* wr[4] = {&w0.x, &w1.x, &w2.x, &w3.x};

#pragma unroll
    for (int t = 0; t < 4; t++) {
        int lt = l - 3 + t;
        if (lt < 0) continue;
        const float4 xv = *(const float4*)(xz + (size_t)(b * Ln + lt) * XZW + d4);
        acc[0] = fmaf(xv.x, wr[0][t], acc[0]);
        acc[1] = fmaf(xv.y, wr[1][t], acc[1]);
        acc[2] = fmaf(xv.z, wr[2][t], acc[2]);
        acc[3] = fmaf(xv.w, wr[3][t], acc[3]);
    }
    float4 o = make_float4(siluf_(acc[0]), siluf_(acc[1]), siluf_(acc[2]), siluf_(acc[3]));
    *(float4*)(xc + (size_t)row * DIn + d4) = o;
}

// =========================================================================
// Chunked selective scan.
// Recurrence per (b,d,n): h_t = a_t*h_{t-1} + u_t, a_t = exp(dlt*A_n),
// u_t = dlt*x_t*B_t[n].  Pass A: per-chunk (P = prod a, S = endpoint | h0=0).
// Pass B: serial prefix over chunks -> per-chunk h0. Pass C: replay + output.
// unit = (chunk c, channel ch); warp = 2 units (16 lanes = states each).
// =========================================================================
__global__ void __launch_bounds__(256) scanA_kernel(
    const float* __restrict__ xdbl,
    const float* __restrict__ delta,
    const float* __restrict__ xc,
    const float* __restrict__ A_log,
    float* __restrict__ Pout,
    float* __restrict__ Sout)
{
    const int tid  = threadIdx.x;
    const int warp = tid >> 5, lane = tid & 31;
    const int grp  = lane >> 4, n = lane & 15;
    const int unit = blockIdx.x * 16 + warp * 2 + grp;   // 0 .. CH*NC-1
    const int ch   = unit & (CH - 1);
    const int c    = unit >> 11;                          // CH = 2048 = 2^11
    const int b    = ch >> 9, d = ch & 511;

    const float Acoef = -__expf(A_log[d * NST + n]);
    const int t0 = c * CL;
    const float* xdb = xdbl  + ((size_t)b * Ln + t0) * XDW;
    const float* dl  = delta + ((size_t)b * Ln + t0) * DIn + d;
    const float* xcb = xc    + ((size_t)b * Ln + t0) * DIn + d;

    float h = 0.f, P = 1.f;
#pragma unroll 4
    for (int t = 0; t < CL; t++) {
        float Bv  = xdb[t * XDW + 16 + n];
        float dlt = dl[(size_t)t * DIn];
        float xv  = xcb[(size_t)t * DIn];
        float a   = __expf(dlt * Acoef);
        h = fmaf(a, h, (dlt * xv) * Bv);
        P *= a;
    }
    const size_t o = ((size_t)c * CH + ch) * NST + n;
    Pout[o] = P;
    Sout[o] = h;
}

__global__ void __launch_bounds__(256) scanB_kernel(
    const float* __restrict__ P,
    const float* __restrict__ S,
    float* __restrict__ H0)
{
    const int idx = blockIdx.x * blockDim.x + threadIdx.x;  // 0 .. CH*NST-1
    float h = 0.f;
#pragma unroll 4
    for (int c = 0; c < NC; c++) {
        const size_t o = (size_t)c * (CH * NST) + idx;
        H0[o] = h;
        h = fmaf(P[o], h, S[o]);
    }
}

__global__ void __launch_bounds__(256) scanC_kernel(
    const float* __restrict__ xdbl,
    const float* __restrict__ delta,
    const float* __restrict__ xc,
    const float* __restrict__ xz,
    const float* __restrict__ A_log,
    const float* __restrict__ D_p,
    const float* __restrict__ H0,
    float* __restrict__ ys)
{
    const int tid  = threadIdx.x;
    const int warp = tid >> 5, lane = tid & 31;
    const int grp  = lane >> 4, n = lane & 15;
    const int unit = blockIdx.x * 16 + warp * 2 + grp;
    const int ch   = unit & (CH - 1);
    const int c    = unit >> 11;
    const int b    = ch >> 9, d = ch & 511;

    const float Acoef = -__expf(A_log[d * NST + n]);
    const float Dp    = D_p[d];
    const int t0 = c * CL;
    const float* xdb = xdbl  + ((size_t)b * Ln + t0) * XDW;
    const float* dl  = delta + ((size_t)b * Ln + t0) * DIn + d;
    const float* xcb = xc    + ((size_t)b * Ln + t0) * DIn + d;
    const float* zb  = xz    + ((size_t)b * Ln + t0) * XZW + DIn + d;
    float*       yb  = ys    + ((size_t)b * Ln + t0) * DIn + d;

    float h = H0[((size_t)c * CH + ch) * NST + n];
#pragma unroll 2
    for (int t = 0; t < CL; t++) {
        float Bv  = xdb[t * XDW + 16 + n];
        float Cv  = xdb[t * XDW + 32 + n];
        float dlt = dl[(size_t)t * DIn];
        float xv  = xcb[(size_t)t * DIn];
        float a   = __expf(dlt * Acoef);
        h = fmaf(a, h, (dlt * xv) * Bv);
        float p = h * Cv;
        p += __shfl_xor_sync(0xffffffffu, p, 1);
        p += __shfl_xor_sync(0xffffffffu, p, 2);
        p += __shfl_xor_sync(0xffffffffu, p, 4);
        p += __shfl_xor_sync(0xffffffffu, p, 8);
        if (n == 0) {
            float zv = zb[(size_t)t * XZW];
            float y  = p + xv * Dp;
            yb[(size_t)t * DIn] = y * siluf_(zv);
        }
    }
}

// ---------------- residual + LayerNorm ----------------------------------
__global__ void ln_res_kernel(const float* __restrict__ x,
                              const float* __restrict__ r,
                              const float* __restrict__ w,
                              const float* __restrict__ bb,
                              float* __restrict__ out)
{
    const int row  = blockIdx.x * 8 + (threadIdx.x >> 5);
    const int lane = threadIdx.x & 31;
    const float* xr = x + (size_t)row * Dn;
    const float* rr = r + (size_t)row * Dn;

    float v[8];
#pragma unroll
    for (int p = 0; p < 2; p++) {
        float4 a = *(const float4*)(xr + p * 128 + lane * 4);
        float4 c = *(const float4*)(rr + p * 128 + lane * 4);
        v[p * 4 + 0] = a.x + c.x;
        v[p * 4 + 1] = a.y + c.y;
        v[p * 4 + 2] = a.z + c.z;
        v[p * 4 + 3] = a.w + c.w;
    }
    float s = 0.f;
#pragma unroll
    for (int i = 0; i < 8; i++) s += v[i];
#pragma unroll
    for (int o = 16; o > 0; o >>= 1) s += __shfl_xor_sync(0xffffffffu, s, o);
    float mu = s * (1.f / 256.f);
    float q = 0.f;
#pragma unroll
    for (int i = 0; i < 8; i++) { float dd = v[i] - mu; q = fmaf(dd, dd, q); }
#pragma unroll
    for (int o = 16; o > 0; o >>= 1) q += __shfl_xor_sync(0xffffffffu, q, o);
    float inv = rsqrtf(q * (1.f / 256.f) + 1e-5f);

#pragma unroll
    for (int p = 0; p < 2; p++) {
        int c0 = p * 128 + lane * 4;
        float4 wv = *(const float4*)(w + c0);
        float4 bv = *(const float4*)(bb + c0);
        float4 o;
        o.x = (v[p * 4 + 0] - mu) * inv * wv.x + bv.x;
        o.y = (v[p * 4 + 1] - mu) * inv * wv.y + bv.y;
        o.z = (v[p * 4 + 2] - mu) * inv * wv.z + bv.z;
        o.w = (v[p * 4 + 3] - mu) * inv * wv.w + bv.w;
        *(float4*)(out + (size_t)row * Dn + c0) = o;
    }
}

// ---------------- host launch ----------------
extern "C" void kernel_launch(void* const* d_in, const int* in_sizes, int n_in,
                              void* d_out, int out_size)
{
    const float* query      = (const float*)d_in[0];
    const float* diff_ts    = (const float*)d_in[2];
    const float* W_in       = (const float*)d_in[3];
    const float* conv_w     = (const float*)d_in[4];
    const float* conv_b     = (const float*)d_in[5];
    const float* W_x        = (const float*)d_in[6];
    const float* W_dt       = (const float*)d_in[7];
    const float* b_dt       = (const float*)d_in[8];
    const float* A_log      = (const float*)d_in[9];
    const float* D_p        = (const float*)d_in[10];
    const float* W_out      = (const float*)d_in[11];
    const float* attn_ada_W = (const float*)d_in[12];
    const float* attn_ada_b = (const float*)d_in[13];
    const float* attn_ln_w  = (const float*)d_in[14];
    const float* attn_ln_b  = (const float*)d_in[15];
    const float* ff_W1      = (const float*)d_in[16];
    const float* ff_b1      = (const float*)d_in[17];
    const float* ff_W2      = (const float*)d_in[18];
    const float* ff_b2      = (const float*)d_in[19];
    const float* ff_ln_w    = (const float*)d_in[20];
    const float* ff_ln_b    = (const float*)d_in[21];
    const float* ff_ada_W   = (const float*)d_in[22];
    const float* ff_ada_b   = (const float*)d_in[23];
    float* out = (float*)d_out;

    float* sc = nullptr;
    cudaGetSymbolAddress((void**)&sc, g_scratch);
    float* g_xz    = sc + OFF_XZ;
    float* g_xc    = sc + OFF_XC;
    float* g_xdbl  = sc + OFF_XDBL;
    float* g_delta = sc + OFF_DELTA;
    float* g_ys    = sc + OFF_YS;
    float* g_aq    = sc + OFF_AQ;
    float* g_attn  = sc + OFF_ATTN;
    float* g_q     = sc + OFF_Q;
    float* g_xf    = sc + OFF_XF;
    float* g_ffh   = sc + OFF_FFH;
    float* g_ffo   = sc + OFF_FFO;
    float* g_mvec  = sc + OFF_MVEC;
    float* g_P     = sc + OFF_P;
    float* g_S     = sc + OFF_S;
    float* g_H0    = sc + OFF_H0;

    modvec_kernel<<<NLn * 2 * Bn, 512>>>(diff_ts, attn_ada_W, attn_ada_b,
                                         ff_ada_W, ff_ada_b, g_mvec);

    const int adaln_blocks = (Mn * 64) / 256;   // 4096
    const int conv_blocks  = (Mn * 128) / 256;  // 8192
    const int scan_blocks  = (CH * NC) / 16;    // 8192

    for (int i = 0; i < NLn; i++) {
        const float* qin = (i == 0) ? query : (out + (size_t)(i - 1) * Mn * Dn);

        // AdaLN (attn)
        adaln_kernel<<<adaln_blocks, 256>>>(qin, g_mvec + (size_t)(i * 2 + 0) * Bn * 2 * Dn, g_aq);

        // xz = aq @ W_in.T       (M,1024)
        gemm128_kernel<0, false><<<dim3(XZW / TBN, Mn / TBM), 256>>>(
            g_aq, Dn, W_in + (size_t)i * XZW * Dn, nullptr, g_xz, XZW, Dn);

        // causal conv + silu -> xc (M,512)
        conv_silu_kernel<<<conv_blocks, 256>>>(g_xz, conv_w + (size_t)i * DIn * 4,
                                               conv_b + (size_t)i * DIn, g_xc);

        // x_dbl = xc @ W_x.T     (M,48)
        gemm_nt_kernel<0, false><<<dim3(1, Mn / GBM), 256>>>(
            g_xc, DIn, W_x + (size_t)i * XDW * DIn, nullptr, g_xdbl, Mn, XDW, DIn);

        // delta = softplus(dt @ W_dt.T + b_dt)   (M,512)
        gemm128_kernel<2, true><<<dim3(DIn / TBN, Mn / TBM), 256>>>(
            g_xdbl, XDW, W_dt + (size_t)i * DIn * 16, b_dt + (size_t)i * DIn,
            g_delta, DIn, 16);

        // chunked selective scan
        scanA_kernel<<<scan_blocks, 256>>>(g_xdbl, g_delta, g_xc,
                                           A_log + (size_t)i * DIn * NST, g_P, g_S);
        scanB_kernel<<<(CH * NST) / 256, 256>>>(g_P, g_S, g_H0);
        scanC_kernel<<<scan_blocks, 256>>>(g_xdbl, g_delta, g_xc, g_xz,
                                           A_log + (size_t)i * DIn * NST,
                                           D_p + (size_t)i * DIn, g_H0, g_ys);

        // attn = ys @ W_out.T    (M,256)
        gemm128_kernel<0, false><<<dim3(Dn / TBN, Mn / TBM), 256>>>(
            g_ys, DIn, W_out + (size_t)i * Dn * DIn, nullptr, g_attn, Dn, DIn);

        // query = LN(qin + attn)
        ln_res_kernel<<<Mn / 8, 256>>>(qin, g_attn, attn_ln_w + (size_t)i * Dn,
                                       attn_ln_b + (size_t)i * Dn, g_q);

        // AdaLN (ff)
        adaln_kernel<<<adaln_blocks, 256>>>(g_q, g_mvec + (size_t)(i * 2 + 1) * Bn * 2 * Dn, g_xf);

        // h = relu(xf @ ff_W1.T + b1)
        gemm128_kernel<1, true><<<dim3(Dn / TBN, Mn / TBM), 256>>>(
            g_xf, Dn, ff_W1 + (size_t)i * Dn * Dn, ff_b1 + (size_t)i * Dn, g_ffh, Dn, Dn);

        // o = h @ ff_W2.T + b2
        gemm128_kernel<0, true><<<dim3(Dn / TBN, Mn / TBM), 256>>>(
            g_ffh, Dn, ff_W2 + (size_t)i * Dn * Dn, ff_b2 + (size_t)i * Dn, g_ffo, Dn, Dn);

        // layer output = LN(xf + o)
        ln_res_kernel<<<Mn / 8, 256>>>(g_xf, g_ffo, ff_ln_w + (size_t)i * Dn,
                                       ff_ln_b + (size_t)i * Dn, out + (size_t)i * Mn * Dn);
    }
}

// round 10
// speedup vs baseline: 5.3549x; 1.2909x over previous
#include <cuda_runtime.h>
#include <math.h>
#include <stdint.h>

// Problem constants
#define Bn     4
#define Ln     4096
#define Dn     256
#define DIn    512
#define NST    16
#define Mn     (Bn * Ln)      // 16384
#define XZW    (2 * DIn)      // 1024
#define XDW    48             // dt_rank + 2*n = 16 + 32
#define NLn    4
#define CH     (Bn * DIn)     // 2048 scan channels
#define NC     64             // scan chunks
#define CL     64             // chunk length

// ---------------- scratch ----------------
#define OFF_XZ     0u
#define OFF_XC     16777216u
#define OFF_XDBL   25165824u
#define OFF_DELTA  25952256u
#define OFF_YS     34340864u
#define OFF_AQ     42729472u
#define OFF_ATTN   46923776u
#define OFF_Q      51118080u
#define OFF_XF     55312384u
#define OFF_FFH    59506688u
#define OFF_FFO    63700992u
#define OFF_MVEC   67895296u
#define OFF_P      67911680u
#define OFF_S      70008832u
#define OFF_H0     72105984u
#define SCRATCH_TOTAL 74203136u

__device__ __align__(16) float g_scratch[SCRATCH_TOTAL];

// ---------------- math helpers ----------------
__device__ __forceinline__ float sigmoidf_(float x) { return 1.f / (1.f + __expf(-x)); }
__device__ __forceinline__ float siluf_(float x)    { return x * sigmoidf_(x); }
__device__ __forceinline__ float softplusf_(float x){ return fmaxf(x, 0.f) + log1pf(__expf(-fabsf(x))); }

__device__ __forceinline__ uint32_t to_tf32_(float f) {
    uint32_t r;
    asm("cvt.rna.tf32.f32 %0, %1;" : "=r"(r) : "f"(f));
    return r;
}

// =========================================================================
// TF32 mma.sync GEMM: C[m,n] = act( sum_k A[m,k]*W[n,k] + bias[n] )
// A (M,K) K-contig; W (N,K) K-contig. Block tile 128x128x32, 8 warps,
// warp tile 64x32 = 4x4 m16n8k8 fragments. Pad-36 smem, conflict-free LDS.
// Requires M%128==0, N%128==0, K%32==0.
// =========================================================================
#define PAD 36

template <int ACT, bool HAS_BIAS>
__global__ void __launch_bounds__(256) gemm_mma_kernel(
    const float* __restrict__ A,
    const float* __restrict__ W,
    const float* __restrict__ bias,
    float* __restrict__ C,
    int Ntot, int Ktot)
{
    __shared__ float As[128][PAD];
    __shared__ float Bs[128][PAD];

    const int tid  = threadIdx.x;
    const int wid  = tid >> 5;
    const int lane = tid & 31;
    const int lr   = lane >> 2;     // 0..7
    const int lc   = lane & 3;      // 0..3
    const int wm   = (wid & 1) * 64;
    const int wn   = (wid >> 1) * 32;
    const int bm   = blockIdx.y * 128;
    const int bn   = blockIdx.x * 128;

    // gmem->smem assignment: row = tid>>1 (0..127), half = (tid&1)*16 floats
    const int grow = tid >> 1;
    const int ghal = (tid & 1) * 16;
    const float* Ap = A + (size_t)(bm + grow) * Ktot + ghal;
    const float* Wp = W + (size_t)(bn + grow) * Ktot + ghal;

    float acc[4][4][4];
#pragma unroll
    for (int i = 0; i < 4; i++)
#pragma unroll
        for (int j = 0; j < 4; j++)
#pragma unroll
            for (int q = 0; q < 4; q++) acc[i][j][q] = 0.f;

    const int KT = Ktot >> 5;
    for (int kt = 0; kt < KT; kt++) {
        const int k0 = kt << 5;
        float4 av[4], wv[4];
#pragma unroll
        for (int q = 0; q < 4; q++) {
            av[q] = *(const float4*)(Ap + k0 + q * 4);
            wv[q] = *(const float4*)(Wp + k0 + q * 4);
        }
        __syncthreads();
#pragma unroll
        for (int q = 0; q < 4; q++) {
            uint32_t* as = (uint32_t*)&As[grow][ghal + q * 4];
            uint32_t* bs = (uint32_t*)&Bs[grow][ghal + q * 4];
            as[0] = to_tf32_(av[q].x); as[1] = to_tf32_(av[q].y);
            as[2] = to_tf32_(av[q].z); as[3] = to_tf32_(av[q].w);
            bs[0] = to_tf32_(wv[q].x); bs[1] = to_tf32_(wv[q].y);
            bs[2] = to_tf32_(wv[q].z); bs[3] = to_tf32_(wv[q].w);
        }
        __syncthreads();

#pragma unroll
        for (int ks = 0; ks < 4; ks++) {
            const int kc = ks * 8 + lc;
            uint32_t a[4][4], b[4][2];
#pragma unroll
            for (int i = 0; i < 4; i++) {
                const int r0 = wm + i * 16 + lr;
                a[i][0] = __float_as_uint(As[r0][kc]);
                a[i][1] = __float_as_uint(As[r0 + 8][kc]);
                a[i][2] = __float_as_uint(As[r0][kc + 4]);
                a[i][3] = __float_as_uint(As[r0 + 8][kc + 4]);
            }
#pragma unroll
            for (int j = 0; j < 4; j++) {
                const int n0 = wn + j * 8 + lr;
                b[j][0] = __float_as_uint(Bs[n0][kc]);
                b[j][1] = __float_as_uint(Bs[n0][kc + 4]);
            }
#pragma unroll
            for (int i = 0; i < 4; i++)
#pragma unroll
                for (int j = 0; j < 4; j++) {
                    asm volatile(
                        "mma.sync.aligned.m16n8k8.row.col.f32.tf32.tf32.f32 "
                        "{%0, %1, %2, %3}, {%4, %5, %6, %7}, {%8, %9}, {%0, %1, %2, %3};"
                        : "+f"(acc[i][j][0]), "+f"(acc[i][j][1]),
                          "+f"(acc[i][j][2]), "+f"(acc[i][j][3])
                        : "r"(a[i][0]), "r"(a[i][1]), "r"(a[i][2]), "r"(a[i][3]),
                          "r"(b[j][0]), "r"(b[j][1]));
                }
        }
    }

    // epilogue
#pragma unroll
    for (int i = 0; i < 4; i++) {
        const int r0 = bm + wm + i * 16 + lr;
#pragma unroll
        for (int j = 0; j < 4; j++) {
            const int c0 = bn + wn + j * 8 + 2 * lc;
            float v0 = acc[i][j][0], v1 = acc[i][j][1];
            float v2 = acc[i][j][2], v3 = acc[i][j][3];
            if (HAS_BIAS) {
                float2 bv = *(const float2*)(bias + c0);
                v0 += bv.x; v1 += bv.y; v2 += bv.x; v3 += bv.y;
            }
            if (ACT == 1) {
                v0 = fmaxf(v0, 0.f); v1 = fmaxf(v1, 0.f);
                v2 = fmaxf(v2, 0.f); v3 = fmaxf(v3, 0.f);
            }
            if (ACT == 2) {
                v0 = softplusf_(v0); v1 = softplusf_(v1);
                v2 = softplusf_(v2); v3 = softplusf_(v3);
            }
            *(float2*)(C + (size_t)r0 * Ntot + c0)       = make_float2(v0, v1);
            *(float2*)(C + (size_t)(r0 + 8) * Ntot + c0) = make_float2(v2, v3);
        }
    }
}

// ---------------- narrow SIMT GEMM (128x64x16) for x_dbl / delta --------
#define GBM 128
#define GBN 64
#define GBK 16

template <int ACT, bool HAS_BIAS>
__global__ void __launch_bounds__(256) gemm_nt_kernel(
    const float* __restrict__ A, int lda,
    const float* __restrict__ W,
    const float* __restrict__ bias,
    float* __restrict__ C,
    int Mtot, int Ntot, int Ktot)
{
    __shared__ float As[GBK][GBM];
    __shared__ float Ws[GBK][GBN];

    const int tid = threadIdx.x;
    const int tx = tid & 15;
    const int ty = tid >> 4;
    const int bm = blockIdx.y * GBM;
    const int bn = blockIdx.x * GBN;

    float acc[8][4];
#pragma unroll
    for (int i = 0; i < 8; i++)
#pragma unroll
        for (int j = 0; j < 4; j++) acc[i][j] = 0.f;

    for (int k0 = 0; k0 < Ktot; k0 += GBK) {
#pragma unroll
        for (int p = 0; p < 2; p++) {
            int t   = tid + p * 256;
            int row = t >> 2;
            int kc  = (t & 3) << 2;
            const float4 av = *(const float4*)(A + (size_t)(bm + row) * lda + k0 + kc);
            As[kc + 0][row] = av.x;
            As[kc + 1][row] = av.y;
            As[kc + 2][row] = av.z;
            As[kc + 3][row] = av.w;
        }
        {
            int row = tid >> 2;
            int kc  = (tid & 3) << 2;
            int gn  = bn + row;
            float4 wv = make_float4(0.f, 0.f, 0.f, 0.f);
            if (gn < Ntot) wv = *(const float4*)(W + (size_t)gn * Ktot + k0 + kc);
            Ws[kc + 0][row] = wv.x;
            Ws[kc + 1][row] = wv.y;
            Ws[kc + 2][row] = wv.z;
            Ws[kc + 3][row] = wv.w;
        }
        __syncthreads();

#pragma unroll
        for (int kk = 0; kk < GBK; kk++) {
            float4 a0 = *(const float4*)&As[kk][ty * 4];
            float4 a1 = *(const float4*)&As[kk][64 + ty * 4];
            float4 w  = *(const float4*)&Ws[kk][tx * 4];
            float am[8] = {a0.x, a0.y, a0.z, a0.w, a1.x, a1.y, a1.z, a1.w};
            float wn[4] = {w.x, w.y, w.z, w.w};
#pragma unroll
            for (int i = 0; i < 8; i++)
#pragma unroll
                for (int j = 0; j < 4; j++)
                    acc[i][j] = fmaf(am[i], wn[j], acc[i][j]);
        }
        __syncthreads();
    }

    const int n0 = bn + tx * 4;
    if (n0 >= Ntot) return;
    float bz[4] = {0.f, 0.f, 0.f, 0.f};
    if (HAS_BIAS) {
        float4 bv = *(const float4*)(bias + n0);
        bz[0] = bv.x; bz[1] = bv.y; bz[2] = bv.z; bz[3] = bv.w;
    }
#pragma unroll
    for (int i = 0; i < 8; i++) {
        int m = bm + ((i < 4) ? (ty * 4 + i) : (64 + ty * 4 + (i - 4)));
        float v[4];
#pragma unroll
        for (int j = 0; j < 4; j++) {
            float c = acc[i][j] + bz[j];
            if (ACT == 1) c = fmaxf(c, 0.f);
            if (ACT == 2) c = softplusf_(c);
            v[j] = c;
        }
        *(float4*)(C + (size_t)m * Ntot + n0) = make_float4(v[0], v[1], v[2], v[3]);
    }
}

// ---------------- modulation vectors ----------------
__global__ void modvec_kernel(const float* __restrict__ ts,
                              const float* __restrict__ attn_W, const float* __restrict__ attn_b,
                              const float* __restrict__ ff_W,   const float* __restrict__ ff_b,
                              float* __restrict__ mvec)
{
    __shared__ float st[Dn];
    const int layer = blockIdx.x >> 3;
    const int which = (blockIdx.x >> 2) & 1;
    const int b     = blockIdx.x & 3;
    if (threadIdx.x < Dn) {
        float tv = ts[b * Dn + threadIdx.x];
        st[threadIdx.x] = siluf_(tv);
    }
    __syncthreads();
    const int j = threadIdx.x;
    const float* W    = (which ? ff_W : attn_W) + (size_t)layer * 2 * Dn * Dn + (size_t)j * Dn;
    const float* bias = (which ? ff_b : attn_b) + layer * 2 * Dn;
    float acc = bias[j];
#pragma unroll 4
    for (int k = 0; k < Dn; k += 4) {
        float4 wv = *(const float4*)(W + k);
        acc = fmaf(st[k], wv.x, acc);
        acc = fmaf(st[k + 1], wv.y, acc);
        acc = fmaf(st[k + 2], wv.z, acc);
        acc = fmaf(st[k + 3], wv.w, acc);
    }
    mvec[((layer * 2 + which) * Bn + b) * 2 * Dn + j] = acc;
}

// ---------------- AdaLN apply ----------------
__global__ void adaln_kernel(const float* __restrict__ q,
                             const float* __restrict__ mv,
                             float* __restrict__ out)
{
    int idx = blockIdx.x * blockDim.x + threadIdx.x;
    int row = idx >> 6;
    int c4  = (idx & 63) << 2;
    int b   = row >> 12;
    float4 qv = *(const float4*)(q + (size_t)row * Dn + c4);
    float4 s  = *(const float4*)(mv + b * 2 * Dn + c4);
    float4 sh = *(const float4*)(mv + b * 2 * Dn + Dn + c4);
    float4 o;
    o.x = fmaf(qv.x, 1.f + s.x, sh.x);
    o.y = fmaf(qv.y, 1.f + s.y, sh.y);
    o.z = fmaf(qv.z, 1.f + s.z, sh.z);
    o.w = fmaf(qv.w, 1.f + s.w, sh.w);
    *(float4*)(out + (size_t)row * Dn + c4) = o;
}

// ---------------- causal depthwise conv + SiLU ----------------
__global__ void conv_silu_kernel(const float* __restrict__ xz,
                                 const float* __restrict__ cw,
                                 const float* __restrict__ cb,
                                 float* __restrict__ xc)
{
    int idx = blockIdx.x * blockDim.x + threadIdx.x;
    int d4  = (idx & 127) << 2;
    int row = idx >> 7;
    int b   = row >> 12;
    int l   = row & 4095;

    float4 bv = *(const float4*)(cb + d4);
    float acc[4] = {bv.x, bv.y, bv.z, bv.w};
    float4 w0 = *(const float4*)(cw + (d4 + 0) * 4);
    float4 w1 = *(const float4*)(cw + (d4 + 1) * 4);
    float4 w2 = *(const float4*)(cw + (d4 + 2) * 4);
    float4 w3 = *(const float4*)(cw + (d4 + 3) * 4);
    const float* wr[4] = {&w0.x, &w1.x, &w2.x, &w3.x};

#pragma unroll
    for (int t = 0; t < 4; t++) {
        int lt = l - 3 + t;
        if (lt < 0) continue;
        const float4 xv = *(const float4*)(xz + (size_t)(b * Ln + lt) * XZW + d4);
        acc[0] = fmaf(xv.x, wr[0][t], acc[0]);
        acc[1] = fmaf(xv.y, wr[1][t], acc[1]);
        acc[2] = fmaf(xv.z, wr[2][t], acc[2]);
        acc[3] = fmaf(xv.w, wr[3][t], acc[3]);
    }
    float4 o = make_float4(siluf_(acc[0]), siluf_(acc[1]), siluf_(acc[2]), siluf_(acc[3]));
    *(float4*)(xc + (size_t)row * DIn + d4) = o;
}

// ---------------- chunked selective scan ----------------
__global__ void __launch_bounds__(256) scanA_kernel(
    const float* __restrict__ xdbl,
    const float* __restrict__ delta,
    const float* __restrict__ xc,
    const float* __restrict__ A_log,
    float* __restrict__ Pout,
    float* __restrict__ Sout)
{
    const int tid  = threadIdx.x;
    const int warp = tid >> 5, lane = tid & 31;
    const int grp  = lane >> 4, n = lane & 15;
    const int unit = blockIdx.x * 16 + warp * 2 + grp;
    const int ch   = unit & (CH - 1);
    const int c    = unit >> 11;
    const int b    = ch >> 9, d = ch & 511;

    const float Acoef = -__expf(A_log[d * NST + n]);
    const int t0 = c * CL;
    const float* xdb = xdbl  + ((size_t)b * Ln + t0) * XDW;
    const float* dl  = delta + ((size_t)b * Ln + t0) * DIn + d;
    const float* xcb = xc    + ((size_t)b * Ln + t0) * DIn + d;

    float h = 0.f, P = 1.f;
#pragma unroll 4
    for (int t = 0; t < CL; t++) {
        float Bv  = xdb[t * XDW + 16 + n];
        float dlt = dl[(size_t)t * DIn];
        float xv  = xcb[(size_t)t * DIn];
        float a   = __expf(dlt * Acoef);
        h = fmaf(a, h, (dlt * xv) * Bv);
        P *= a;
    }
    const size_t o = ((size_t)c * CH + ch) * NST + n;
    Pout[o] = P;
    Sout[o] = h;
}

__global__ void __launch_bounds__(256) scanB_kernel(
    const float* __restrict__ P,
    const float* __restrict__ S,
    float* __restrict__ H0)
{
    const int idx = blockIdx.x * blockDim.x + threadIdx.x;
    float h = 0.f;
#pragma unroll 4
    for (int c = 0; c < NC; c++) {
        const size_t o = (size_t)c * (CH * NST) + idx;
        H0[o] = h;
        h = fmaf(P[o], h, S[o]);
    }
}

__global__ void __launch_bounds__(256) scanC_kernel(
    const float* __restrict__ xdbl,
    const float* __restrict__ delta,
    const float* __restrict__ xc,
    const float* __restrict__ xz,
    const float* __restrict__ A_log,
    const float* __restrict__ D_p,
    const float* __restrict__ H0,
    float* __restrict__ ys)
{
    const int tid  = threadIdx.x;
    const int warp = tid >> 5, lane = tid & 31;
    const int grp  = lane >> 4, n = lane & 15;
    const int unit = blockIdx.x * 16 + warp * 2 + grp;
    const int ch   = unit & (CH - 1);
    const int c    = unit >> 11;
    const int b    = ch >> 9, d = ch & 511;

    const float Acoef = -__expf(A_log[d * NST + n]);
    const float Dp    = D_p[d];
    const int t0 = c * CL;
    const float* xdb = xdbl  + ((size_t)b * Ln + t0) * XDW;
    const float* dl  = delta + ((size_t)b * Ln + t0) * DIn + d;
    const float* xcb = xc    + ((size_t)b * Ln + t0) * DIn + d;
    const float* zb  = xz    + ((size_t)b * Ln + t0) * XZW + DIn + d;
    float*       yb  = ys    + ((size_t)b * Ln + t0) * DIn + d;

    float h = H0[((size_t)c * CH + ch) * NST + n];
#pragma unroll 2
    for (int t = 0; t < CL; t++) {
        float Bv  = xdb[t * XDW + 16 + n];
        float Cv  = xdb[t * XDW + 32 + n];
        float dlt = dl[(size_t)t * DIn];
        float xv  = xcb[(size_t)t * DIn];
        float a   = __expf(dlt * Acoef);
        h = fmaf(a, h, (dlt * xv) * Bv);
        float p = h * Cv;
        p += __shfl_xor_sync(0xffffffffu, p, 1);
        p += __shfl_xor_sync(0xffffffffu, p, 2);
        p += __shfl_xor_sync(0xffffffffu, p, 4);
        p += __shfl_xor_sync(0xffffffffu, p, 8);
        if (n == 0) {
            float zv = zb[(size_t)t * XZW];
            float y  = p + xv * Dp;
            yb[(size_t)t * DIn] = y * siluf_(zv);
        }
    }
}

// ---------------- residual + LayerNorm ----------------
__global__ void ln_res_kernel(const float* __restrict__ x,
                              const float* __restrict__ r,
                              const float* __restrict__ w,
                              const float* __restrict__ bb,
                              float* __restrict__ out)
{
    const int row  = blockIdx.x * 8 + (threadIdx.x >> 5);
    const int lane = threadIdx.x & 31;
    const float* xr = x + (size_t)row * Dn;
    const float* rr = r + (size_t)row * Dn;

    float v[8];
#pragma unroll
    for (int p = 0; p < 2; p++) {
        float4 a = *(const float4*)(xr + p * 128 + lane * 4);
        float4 c = *(const float4*)(rr + p * 128 + lane * 4);
        v[p * 4 + 0] = a.x + c.x;
        v[p * 4 + 1] = a.y + c.y;
        v[p * 4 + 2] = a.z + c.z;
        v[p * 4 + 3] = a.w + c.w;
    }
    float s = 0.f;
#pragma unroll
    for (int i = 0; i < 8; i++) s += v[i];
#pragma unroll
    for (int o = 16; o > 0; o >>= 1) s += __shfl_xor_sync(0xffffffffu, s, o);
    float mu = s * (1.f / 256.f);
    float q = 0.f;
#pragma unroll
    for (int i = 0; i < 8; i++) { float dd = v[i] - mu; q = fmaf(dd, dd, q); }
#pragma unroll
    for (int o = 16; o > 0; o >>= 1) q += __shfl_xor_sync(0xffffffffu, q, o);
    float inv = rsqrtf(q * (1.f / 256.f) + 1e-5f);

#pragma unroll
    for (int p = 0; p < 2; p++) {
        int c0 = p * 128 + lane * 4;
        float4 wv = *(const float4*)(w + c0);
        float4 bv = *(const float4*)(bb + c0);
        float4 o;
        o.x = (v[p * 4 + 0] - mu) * inv * wv.x + bv.x;
        o.y = (v[p * 4 + 1] - mu) * inv * wv.y + bv.y;
        o.z = (v[p * 4 + 2] - mu) * inv * wv.z + bv.z;
        o.w = (v[p * 4 + 3] - mu) * inv * wv.w + bv.w;
        *(float4*)(out + (size_t)row * Dn + c0) = o;
    }
}

// ---------------- host launch ----------------
extern "C" void kernel_launch(void* const* d_in, const int* in_sizes, int n_in,
                              void* d_out, int out_size)
{
    const float* query      = (const float*)d_in[0];
    const float* diff_ts    = (const float*)d_in[2];
    const float* W_in       = (const float*)d_in[3];
    const float* conv_w     = (const float*)d_in[4];
    const float* conv_b     = (const float*)d_in[5];
    const float* W_x        = (const float*)d_in[6];
    const float* W_dt       = (const float*)d_in[7];
    const float* b_dt       = (const float*)d_in[8];
    const float* A_log      = (const float*)d_in[9];
    const float* D_p        = (const float*)d_in[10];
    const float* W_out      = (const float*)d_in[11];
    const float* attn_ada_W = (const float*)d_in[12];
    const float* attn_ada_b = (const float*)d_in[13];
    const float* attn_ln_w  = (const float*)d_in[14];
    const float* attn_ln_b  = (const float*)d_in[15];
    const float* ff_W1      = (const float*)d_in[16];
    const float* ff_b1      = (const float*)d_in[17];
    const float* ff_W2      = (const float*)d_in[18];
    const float* ff_b2      = (const float*)d_in[19];
    const float* ff_ln_w    = (const float*)d_in[20];
    const float* ff_ln_b    = (const float*)d_in[21];
    const float* ff_ada_W   = (const float*)d_in[22];
    const float* ff_ada_b   = (const float*)d_in[23];
    float* out = (float*)d_out;

    float* sc = nullptr;
    cudaGetSymbolAddress((void**)&sc, g_scratch);
    float* g_xz    = sc + OFF_XZ;
    float* g_xc    = sc + OFF_XC;
    float* g_xdbl  = sc + OFF_XDBL;
    float* g_delta = sc + OFF_DELTA;
    float* g_ys    = sc + OFF_YS;
    float* g_aq    = sc + OFF_AQ;
    float* g_attn  = sc + OFF_ATTN;
    float* g_q     = sc + OFF_Q;
    float* g_xf    = sc + OFF_XF;
    float* g_ffh   = sc + OFF_FFH;
    float* g_ffo   = sc + OFF_FFO;
    float* g_mvec  = sc + OFF_MVEC;
    float* g_P     = sc + OFF_P;
    float* g_S     = sc + OFF_S;
    float* g_H0    = sc + OFF_H0;

    modvec_kernel<<<NLn * 2 * Bn, 512>>>(diff_ts, attn_ada_W, attn_ada_b,
                                         ff_ada_W, ff_ada_b, g_mvec);

    const int adaln_blocks = (Mn * 64) / 256;   // 4096
    const int conv_blocks  = (Mn * 128) / 256;  // 8192
    const int scan_blocks  = (CH * NC) / 16;    // 8192

    for (int i = 0; i < NLn; i++) {
        const float* qin = (i == 0) ? query : (out + (size_t)(i - 1) * Mn * Dn);

        // AdaLN (attn)
        adaln_kernel<<<adaln_blocks, 256>>>(qin, g_mvec + (size_t)(i * 2 + 0) * Bn * 2 * Dn, g_aq);

        // xz = aq @ W_in.T       (M,1024) K=256   [TF32 mma]
        gemm_mma_kernel<0, false><<<dim3(XZW / 128, Mn / 128), 256>>>(
            g_aq, W_in + (size_t)i * XZW * Dn, nullptr, g_xz, XZW, Dn);

        // causal conv + silu -> xc (M,512)
        conv_silu_kernel<<<conv_blocks, 256>>>(g_xz, conv_w + (size_t)i * DIn * 4,
                                               conv_b + (size_t)i * DIn, g_xc);

        // x_dbl = xc @ W_x.T     (M,48) K=512     [SIMT, exact]
        gemm_nt_kernel<0, false><<<dim3(1, Mn / GBM), 256>>>(
            g_xc, DIn, W_x + (size_t)i * XDW * DIn, nullptr, g_xdbl, Mn, XDW, DIn);

        // delta = softplus(dt @ W_dt.T + b_dt)  (M,512) K=16  [SIMT, exact]
        gemm_nt_kernel<2, true><<<dim3(DIn / GBN, Mn / GBM), 256>>>(
            g_xdbl, XDW, W_dt + (size_t)i * DIn * 16, b_dt + (size_t)i * DIn,
            g_delta, Mn, DIn, 16);

        // chunked selective scan
        scanA_kernel<<<scan_blocks, 256>>>(g_xdbl, g_delta, g_xc,
                                           A_log + (size_t)i * DIn * NST, g_P, g_S);
        scanB_kernel<<<(CH * NST) / 256, 256>>>(g_P, g_S, g_H0);
        scanC_kernel<<<scan_blocks, 256>>>(g_xdbl, g_delta, g_xc, g_xz,
                                           A_log + (size_t)i * DIn * NST,
                                           D_p + (size_t)i * DIn, g_H0, g_ys);

        // attn = ys @ W_out.T    (M,256) K=512    [TF32 mma]
        gemm_mma_kernel<0, false><<<dim3(Dn / 128, Mn / 128), 256>>>(
            g_ys, W_out + (size_t)i * Dn * DIn, nullptr, g_attn, Dn, DIn);

        // query = LN(qin + attn)
        ln_res_kernel<<<Mn / 8, 256>>>(qin, g_attn, attn_ln_w + (size_t)i * Dn,
                                       attn_ln_b + (size_t)i * Dn, g_q);

        // AdaLN (ff)
        adaln_kernel<<<adaln_blocks, 256>>>(g_q, g_mvec + (size_t)(i * 2 + 1) * Bn * 2 * Dn, g_xf);

        // h = relu(xf @ ff_W1.T + b1)   (M,256) K=256   [TF32 mma]
        gemm_mma_kernel<1, true><<<dim3(Dn / 128, Mn / 128), 256>>>(
            g_xf, ff_W1 + (size_t)i * Dn * Dn, ff_b1 + (size_t)i * Dn, g_ffh, Dn, Dn);

        // o = h @ ff_W2.T + b2          (M,256) K=256   [TF32 mma]
        gemm_mma_kernel<0, true><<<dim3(Dn / 128, Mn / 128), 256>>>(
            g_ffh, ff_W2 + (size_t)i * Dn * Dn, ff_b2 + (size_t)i * Dn, g_ffo, Dn, Dn);

        // layer output = LN(xf + o)
        ln_res_kernel<<<Mn / 8, 256>>>(g_xf, g_ffo, ff_ln_w + (size_t)i * Dn,
                                       ff_ln_b + (size_t)i * Dn, out + (size_t)i * Mn * Dn);
    }
}